// round 16
// baseline (speedup 1.0000x reference)
#include <cuda_runtime.h>
#include <cuda_fp16.h>
#include <cstdint>

#define D_IN     256
#define H_DIM    128
#define N_SHARE  4
#define N_EXPERTS 12
#define M_TILE   64
#define THREADS  256

// fragment-ordered fp16 weight image: [12][16ks][8ng][32lane][16B]
__device__ __align__(16) __half g_Wh[N_EXPERTS * 32768];
// fragment-ordered fp16 gate-weight image: [16ks][32lane][16B] (N=16)
__device__ __align__(16) __half g_Wgh[4096];

// ---- shared memory layout (bytes) ----
#define OFF_A    0          // 32768: [16ks][4mb][32lane][16B]
#define OFF_GS   32768      // gates [64][17] f32 = 4352
#define OFF_BS   37120      // biases [12][128] f32 = 6144
#define SMEM_BYTES 43264

static __device__ __forceinline__ void mma_f16(float* d, const uint32_t* a,
                                               uint32_t b0, uint32_t b1) {
    asm volatile(
        "mma.sync.aligned.m16n8k16.row.col.f32.f16.f16.f32 "
        "{%0,%1,%2,%3}, {%4,%5,%6,%7}, {%8,%9}, {%0,%1,%2,%3};\n"
        : "+f"(d[0]), "+f"(d[1]), "+f"(d[2]), "+f"(d[3])
        : "r"(a[0]), "r"(a[1]), "r"(a[2]), "r"(a[3]), "r"(b0), "r"(b1));
}
static __device__ __forceinline__ uint32_t h2u(float lo, float hi) {
    half2 h = __floats2half2_rn(lo, hi);
    return *(uint32_t*)&h;
}

// ---------------- weight prep: fp16 fragment-ordered images ----------------
__global__ void dmoe_wprep(const float* __restrict__ Wsh,
                           const float* __restrict__ Wtk,
                           const float* __restrict__ Wg) {
    int idx = blockIdx.x * 256 + threadIdx.x;     // slot index
    if (idx < N_EXPERTS * 4096) {
        int e = idx >> 12;
        int s = idx & 4095;
        int lane = s & 31, ng = (s >> 5) & 7, ks = s >> 8;
        int gid = lane >> 2, tig = lane & 3;
        int k0 = ks * 16 + tig * 2;
        int na = ng * 16 + gid, nb = na + 8;
        const float* W = (e < N_SHARE)
            ? (Wsh + (size_t)e * (D_IN * H_DIM))
            : (Wtk + (size_t)(e - N_SHARE) * (D_IN * H_DIM));
        uint4 v;
        v.x = h2u(W[(size_t)k0 * H_DIM + na],     W[(size_t)(k0+1) * H_DIM + na]);
        v.y = h2u(W[(size_t)(k0+8) * H_DIM + na], W[(size_t)(k0+9) * H_DIM + na]);
        v.z = h2u(W[(size_t)k0 * H_DIM + nb],     W[(size_t)(k0+1) * H_DIM + nb]);
        v.w = h2u(W[(size_t)(k0+8) * H_DIM + nb], W[(size_t)(k0+9) * H_DIM + nb]);
        *(uint4*)((char*)g_Wh + (size_t)e * 65536 + (size_t)s * 16) = v;
    } else if (idx < N_EXPERTS * 4096 + 512) {
        int s = idx - N_EXPERTS * 4096;           // 0..511
        int lane = s & 31, ks = s >> 5;           // ks 0..15
        int gid = lane >> 2, tig = lane & 3;
        int k0 = ks * 16 + tig * 2;
        int na = gid, nb = gid + 8;
        #define GV(k, n) Wg[((n) >> 3) * 2048 + (k) * 8 + ((n) & 7)]
        uint4 v;
        v.x = h2u(GV(k0, na),     GV(k0 + 1, na));
        v.y = h2u(GV(k0 + 8, na), GV(k0 + 9, na));
        v.z = h2u(GV(k0, nb),     GV(k0 + 1, nb));
        v.w = h2u(GV(k0 + 8, nb), GV(k0 + 9, nb));
        #undef GV
        *(uint4*)((char*)g_Wgh + s * 16) = v;
    }
}

// ---------------- main fused kernel ----------------
__global__ __launch_bounds__(THREADS, 3)
void dmoe_fused_kernel(const float* __restrict__ x,
                       const float* __restrict__ bsh,
                       const float* __restrict__ btk,
                       const float* __restrict__ bg,
                       float* __restrict__ out,
                       int Btot)
{
    extern __shared__ char smem[];
    float* gs = (float*)(smem + OFF_GS);
    float* bs = (float*)(smem + OFF_BS);

    const int tid  = threadIdx.x;
    const int warp = tid >> 5;
    const int lane = tid & 31;
    const int gid  = lane >> 2;
    const int tig  = lane & 3;
    const int m0   = (warp >> 2) * 32;       // 0 or 32
    const int mbA  = (warp >> 2) * 2;        // A m-block base (16-row blocks)
    const int hb   = warp & 3;               // 32-col h block
    const int row0 = blockIdx.x * M_TILE;

    // --- stage x tile (64 x 256) into fp16 A-fragment order
    {
        #pragma unroll
        for (int j = 0; j < 8; ++j) {
            int s = j * THREADS + tid;       // 2048 slots
            int ln = s & 31, mb = (s >> 5) & 3, ks = s >> 7;
            int g = ln >> 2, tg = ln & 3;
            int r = row0 + mb * 16 + g;
            int k0 = ks * 16 + tg * 2;
            const float* xp = x + (size_t)r * D_IN;
            float2 v00 = *(const float2*)(xp + k0);
            float2 v10 = *(const float2*)(xp + 8 * D_IN + k0);
            float2 v01 = *(const float2*)(xp + k0 + 8);
            float2 v11 = *(const float2*)(xp + 8 * D_IN + k0 + 8);
            uint4 a;
            a.x = h2u(v00.x, v00.y);
            a.y = h2u(v10.x, v10.y);
            a.z = h2u(v01.x, v01.y);
            a.w = h2u(v11.x, v11.y);
            *(uint4*)(smem + OFF_A + (size_t)s * 16) = a;
        }
    }
    // --- biases
    for (int i = tid; i < N_EXPERTS * H_DIM; i += THREADS) {
        int e = i >> 7, h = i & 127;
        bs[i] = (e < N_SHARE) ? bsh[e * H_DIM + h]
                              : btk[(e - N_SHARE) * H_DIM + h];
    }
    __syncthreads();

    const char* ap    = smem + OFF_A + mbA * 512 + lane * 16;
    const char* bbase = (const char*)g_Wh + (size_t)(2 * hb) * 512 + (size_t)lane * 16;

    // --- gates on the tensor core: logits[32 rows][16] from staged A
    {
        float ga[2][2][4];
        #pragma unroll
        for (int mt = 0; mt < 2; ++mt)
            #pragma unroll
            for (int g2 = 0; g2 < 2; ++g2)
                #pragma unroll
                for (int c = 0; c < 4; ++c)
                    ga[mt][g2][c] = 0.f;
        const char* gwp = (const char*)g_Wgh + lane * 16;
        #pragma unroll 4
        for (int ks = 0; ks < 16; ++ks) {
            uint4 A0 = *(const uint4*)(ap + ks * 2048);
            uint4 A1 = *(const uint4*)(ap + ks * 2048 + 512);
            uint4 G  = __ldg((const uint4*)(gwp + ks * 512));
            const uint32_t* ua0 = (const uint32_t*)&A0;
            const uint32_t* ua1 = (const uint32_t*)&A1;
            mma_f16(ga[0][0], ua0, G.x, G.y);
            mma_f16(ga[0][1], ua0, G.z, G.w);
            mma_f16(ga[1][0], ua1, G.x, G.y);
            mma_f16(ga[1][1], ua1, G.z, G.w);
        }
        float bg0a = bg[tig * 2],     bg0b = bg[tig * 2 + 1];
        float bg1a = bg[8 + tig * 2], bg1b = bg[9 + tig * 2];
        #pragma unroll
        for (int mt = 0; mt < 2; ++mt) {
            #pragma unroll
            for (int hf = 0; hf < 2; ++hf) {
                int row = m0 + mt * 16 + hf * 8 + gid;
                float l0a = ga[mt][0][hf * 2]     + bg0a;
                float l0b = ga[mt][0][hf * 2 + 1] + bg0b;
                float l1a = ga[mt][1][hf * 2]     + bg1a;
                float l1b = ga[mt][1][hf * 2 + 1] + bg1b;
                float mx0 = fmaxf(l0a, l0b);
                mx0 = fmaxf(mx0, __shfl_xor_sync(0xffffffffu, mx0, 1));
                mx0 = fmaxf(mx0, __shfl_xor_sync(0xffffffffu, mx0, 2));
                float e0a = __expf(l0a - mx0), e0b = __expf(l0b - mx0);
                float s0 = e0a + e0b;
                s0 += __shfl_xor_sync(0xffffffffu, s0, 1);
                s0 += __shfl_xor_sync(0xffffffffu, s0, 2);
                float inv0 = 1.f / s0;
                gs[row * 17 + tig * 2]     = e0a * inv0;
                gs[row * 17 + tig * 2 + 1] = e0b * inv0;
                float mx1 = fmaxf(l1a, l1b);
                mx1 = fmaxf(mx1, __shfl_xor_sync(0xffffffffu, mx1, 1));
                mx1 = fmaxf(mx1, __shfl_xor_sync(0xffffffffu, mx1, 2));
                float e1a = __expf(l1a - mx1), e1b = __expf(l1b - mx1);
                float s1 = e1a + e1b;
                s1 += __shfl_xor_sync(0xffffffffu, s1, 1);
                s1 += __shfl_xor_sync(0xffffffffu, s1, 2);
                float inv1 = 1.f / s1;
                gs[row * 17 + 8 + tig * 2] = e1a * inv1;
                gs[row * 17 + 9 + tig * 2] = e1b * inv1;
            }
        }
    }
    __syncthreads();
    // ======= no further barriers: pure dataflow from here on =======

    // --- main loop: 12 experts; 32m x 32n per warp; global RMW epilogue
    #pragma unroll 1
    for (int e = 0; e < N_EXPERTS; ++e) {
        float acc[2][4][4];
        #pragma unroll
        for (int mt = 0; mt < 2; ++mt)
            #pragma unroll
            for (int nt = 0; nt < 4; ++nt)
                #pragma unroll
                for (int c = 0; c < 4; ++c)
                    acc[mt][nt][c] = 0.f;

        const char* bp = bbase + (size_t)e * 65536;
        #pragma unroll 4
        for (int ks = 0; ks < 16; ++ks) {
            uint4 A0 = *(const uint4*)(ap + ks * 2048);
            uint4 A1 = *(const uint4*)(ap + ks * 2048 + 512);
            uint4 B0 = __ldg((const uint4*)(bp + ks * 4096));
            uint4 B1 = __ldg((const uint4*)(bp + ks * 4096 + 512));
            const uint32_t* ua0 = (const uint32_t*)&A0;
            const uint32_t* ua1 = (const uint32_t*)&A1;
            mma_f16(acc[0][0], ua0, B0.x, B0.y);
            mma_f16(acc[0][1], ua0, B0.z, B0.w);
            mma_f16(acc[0][2], ua0, B1.x, B1.y);
            mma_f16(acc[0][3], ua0, B1.z, B1.w);
            mma_f16(acc[1][0], ua1, B0.x, B0.y);
            mma_f16(acc[1][1], ua1, B0.z, B0.w);
            mma_f16(acc[1][2], ua1, B1.x, B1.y);
            mma_f16(acc[1][3], ua1, B1.z, B1.w);
        }

        // --- epilogue: bias + ReLU + gate-scaled global RMW (warp-exclusive region)
        #pragma unroll
        for (int mt = 0; mt < 2; ++mt) {
            int rA = m0 + mt * 16 + gid;
            int rB = rA + 8;
            float* oA0 = out + ((size_t)row0 + rA) * H_DIM;
            float* oB0 = out + ((size_t)row0 + rB) * H_DIM;
            float* oA1 = oA0 + (size_t)Btot * H_DIM;
            float* oB1 = oB0 + (size_t)Btot * H_DIM;
            if (e < N_SHARE) {
                float gA0 = gs[rA * 17 + e],     gB0 = gs[rB * 17 + e];
                float gA1 = gs[rA * 17 + 8 + e], gB1 = gs[rB * 17 + 8 + e];
                #pragma unroll
                for (int nt = 0; nt < 4; ++nt) {
                    int h = hb * 32 + nt * 8 + tig * 2;
                    float b0 = bs[e * H_DIM + h];
                    float b1 = bs[e * H_DIM + h + 1];
                    float v0 = fmaxf(acc[mt][nt][0] + b0, 0.f);
                    float v1 = fmaxf(acc[mt][nt][1] + b1, 0.f);
                    float v2 = fmaxf(acc[mt][nt][2] + b0, 0.f);
                    float v3 = fmaxf(acc[mt][nt][3] + b1, 0.f);
                    if (e == 0) {
                        *(float2*)(oA0 + h) = make_float2(gA0 * v0, gA0 * v1);
                        *(float2*)(oB0 + h) = make_float2(gB0 * v2, gB0 * v3);
                        *(float2*)(oA1 + h) = make_float2(gA1 * v0, gA1 * v1);
                        *(float2*)(oB1 + h) = make_float2(gB1 * v2, gB1 * v3);
                    } else {
                        float2 p;
                        p = *(float2*)(oA0 + h);
                        p.x += gA0 * v0; p.y += gA0 * v1;
                        *(float2*)(oA0 + h) = p;
                        p = *(float2*)(oB0 + h);
                        p.x += gB0 * v2; p.y += gB0 * v3;
                        *(float2*)(oB0 + h) = p;
                        p = *(float2*)(oA1 + h);
                        p.x += gA1 * v0; p.y += gA1 * v1;
                        *(float2*)(oA1 + h) = p;
                        p = *(float2*)(oB1 + h);
                        p.x += gB1 * v2; p.y += gB1 * v3;
                        *(float2*)(oB1 + h) = p;
                    }
                }
            } else {
                int et = e - N_SHARE;
                int tt = et >> 2;
                int gcol = tt * 8 + 4 + (et & 3);
                float gA = gs[rA * 17 + gcol];
                float gB = gs[rB * 17 + gcol];
                float* oA = tt ? oA1 : oA0;
                float* oB = tt ? oB1 : oB0;
                #pragma unroll
                for (int nt = 0; nt < 4; ++nt) {
                    int h = hb * 32 + nt * 8 + tig * 2;
                    float b0 = bs[e * H_DIM + h];
                    float b1 = bs[e * H_DIM + h + 1];
                    float2 p;
                    p = *(float2*)(oA + h);
                    p.x += gA * fmaxf(acc[mt][nt][0] + b0, 0.f);
                    p.y += gA * fmaxf(acc[mt][nt][1] + b1, 0.f);
                    *(float2*)(oA + h) = p;
                    p = *(float2*)(oB + h);
                    p.x += gB * fmaxf(acc[mt][nt][2] + b0, 0.f);
                    p.y += gB * fmaxf(acc[mt][nt][3] + b1, 0.f);
                    *(float2*)(oB + h) = p;
                }
            }
        }
    }
}

extern "C" void kernel_launch(void* const* d_in, const int* in_sizes, int n_in,
                              void* d_out, int out_size) {
    const float* x   = (const float*)d_in[0];
    const float* Wsh = (const float*)d_in[1];
    const float* bsh = (const float*)d_in[2];
    const float* Wtk = (const float*)d_in[3];
    const float* btk = (const float*)d_in[4];
    const float* Wg  = (const float*)d_in[5];
    const float* bg  = (const float*)d_in[6];
    float* out = (float*)d_out;

    int Btot = in_sizes[0] / D_IN;                // 32768
    int nslots = N_EXPERTS * 4096 + 512;          // 49664
    dmoe_wprep<<<(nslots + 255) / 256, 256>>>(Wsh, Wtk, Wg);

    cudaFuncSetAttribute(dmoe_fused_kernel,
                         cudaFuncAttributeMaxDynamicSharedMemorySize, SMEM_BYTES);
    dmoe_fused_kernel<<<Btot / M_TILE, THREADS, SMEM_BYTES>>>(
        x, bsh, btk, bg, out, Btot);
}

// round 17
// speedup vs baseline: 2.1104x; 2.1104x over previous
#include <cuda_runtime.h>
#include <cuda_fp16.h>
#include <cstdint>

#define D_IN     256
#define H_DIM    128
#define N_SHARE  4
#define N_EXPERTS 12
#define M_TILE   64
#define THREADS  256

// fragment-ordered fp16 weight image: [12][16ks][8ng][32lane][16B]
__device__ __align__(16) __half g_Wh[N_EXPERTS * 32768];
// fragment-ordered fp16 gate-weight image: [16ks][32lane][16B] (N=16)
__device__ __align__(16) __half g_Wgh[4096];

// ---- shared memory layout (bytes) ----
#define OFF_A    0          // 32768: [16ks][4mb][32lane][16B]
#define OFF_GS   32768      // gates [64][17] f32 = 4352
#define OFF_BS   37120      // biases [12][128] f32 = 6144
#define SMEM_BYTES 43264

static __device__ __forceinline__ void mma_f16(float* d, const uint32_t* a,
                                               uint32_t b0, uint32_t b1) {
    asm volatile(
        "mma.sync.aligned.m16n8k16.row.col.f32.f16.f16.f32 "
        "{%0,%1,%2,%3}, {%4,%5,%6,%7}, {%8,%9}, {%0,%1,%2,%3};\n"
        : "+f"(d[0]), "+f"(d[1]), "+f"(d[2]), "+f"(d[3])
        : "r"(a[0]), "r"(a[1]), "r"(a[2]), "r"(a[3]), "r"(b0), "r"(b1));
}
static __device__ __forceinline__ uint32_t h2u(float lo, float hi) {
    half2 h = __floats2half2_rn(lo, hi);
    return *(uint32_t*)&h;
}

// ---------------- weight prep: fp16 fragment-ordered images ----------------
__global__ void dmoe_wprep(const float* __restrict__ Wsh,
                           const float* __restrict__ Wtk,
                           const float* __restrict__ Wg) {
    int idx = blockIdx.x * 256 + threadIdx.x;     // slot index
    if (idx < N_EXPERTS * 4096) {
        int e = idx >> 12;
        int s = idx & 4095;
        int lane = s & 31, ng = (s >> 5) & 7, ks = s >> 8;
        int gid = lane >> 2, tig = lane & 3;
        int k0 = ks * 16 + tig * 2;
        int na = ng * 16 + gid, nb = na + 8;
        const float* W = (e < N_SHARE)
            ? (Wsh + (size_t)e * (D_IN * H_DIM))
            : (Wtk + (size_t)(e - N_SHARE) * (D_IN * H_DIM));
        uint4 v;
        v.x = h2u(W[(size_t)k0 * H_DIM + na],     W[(size_t)(k0+1) * H_DIM + na]);
        v.y = h2u(W[(size_t)(k0+8) * H_DIM + na], W[(size_t)(k0+9) * H_DIM + na]);
        v.z = h2u(W[(size_t)k0 * H_DIM + nb],     W[(size_t)(k0+1) * H_DIM + nb]);
        v.w = h2u(W[(size_t)(k0+8) * H_DIM + nb], W[(size_t)(k0+9) * H_DIM + nb]);
        *(uint4*)((char*)g_Wh + (size_t)e * 65536 + (size_t)s * 16) = v;
    } else if (idx < N_EXPERTS * 4096 + 512) {
        int s = idx - N_EXPERTS * 4096;           // 0..511
        int lane = s & 31, ks = s >> 5;           // ks 0..15
        int gid = lane >> 2, tig = lane & 3;
        int k0 = ks * 16 + tig * 2;
        int na = gid, nb = gid + 8;
        #define GV(k, n) Wg[((n) >> 3) * 2048 + (k) * 8 + ((n) & 7)]
        uint4 v;
        v.x = h2u(GV(k0, na),     GV(k0 + 1, na));
        v.y = h2u(GV(k0 + 8, na), GV(k0 + 9, na));
        v.z = h2u(GV(k0, nb),     GV(k0 + 1, nb));
        v.w = h2u(GV(k0 + 8, nb), GV(k0 + 9, nb));
        #undef GV
        *(uint4*)((char*)g_Wgh + s * 16) = v;
    }
}

// ---------------- main fused kernel ----------------
__global__ __launch_bounds__(THREADS, 2)
void dmoe_fused_kernel(const float* __restrict__ x,
                       const float* __restrict__ bsh,
                       const float* __restrict__ btk,
                       const float* __restrict__ bg,
                       float* __restrict__ out,
                       int Btot)
{
    extern __shared__ char smem[];
    float* gs = (float*)(smem + OFF_GS);
    float* bs = (float*)(smem + OFF_BS);

    const int tid  = threadIdx.x;
    const int warp = tid >> 5;
    const int lane = tid & 31;
    const int gid  = lane >> 2;
    const int tig  = lane & 3;
    const int m0   = (warp >> 2) * 32;       // 0 or 32
    const int mbA  = (warp >> 2) * 2;        // A m-block base (16-row blocks)
    const int hb   = warp & 3;               // 32-col h block
    const int row0 = blockIdx.x * M_TILE;

    // --- stage x tile (64 x 256) into fp16 A-fragment order
    {
        #pragma unroll
        for (int j = 0; j < 8; ++j) {
            int s = j * THREADS + tid;       // 2048 slots
            int ln = s & 31, mb = (s >> 5) & 3, ks = s >> 7;
            int g = ln >> 2, tg = ln & 3;
            int r = row0 + mb * 16 + g;
            int k0 = ks * 16 + tg * 2;
            const float* xp = x + (size_t)r * D_IN;
            float2 v00 = *(const float2*)(xp + k0);
            float2 v10 = *(const float2*)(xp + 8 * D_IN + k0);
            float2 v01 = *(const float2*)(xp + k0 + 8);
            float2 v11 = *(const float2*)(xp + 8 * D_IN + k0 + 8);
            uint4 a;
            a.x = h2u(v00.x, v00.y);
            a.y = h2u(v10.x, v10.y);
            a.z = h2u(v01.x, v01.y);
            a.w = h2u(v11.x, v11.y);
            *(uint4*)(smem + OFF_A + (size_t)s * 16) = a;
        }
    }
    // --- biases
    for (int i = tid; i < N_EXPERTS * H_DIM; i += THREADS) {
        int e = i >> 7, h = i & 127;
        bs[i] = (e < N_SHARE) ? bsh[e * H_DIM + h]
                              : btk[(e - N_SHARE) * H_DIM + h];
    }
    __syncthreads();

    const char* ap    = smem + OFF_A + mbA * 512 + lane * 16;
    const char* bbase = (const char*)g_Wh + (size_t)(2 * hb) * 512 + (size_t)lane * 16;

    // --- gates on the tensor core: logits[32 rows][16] from staged A
    {
        float ga[2][2][4];
        #pragma unroll
        for (int mt = 0; mt < 2; ++mt)
            #pragma unroll
            for (int g2 = 0; g2 < 2; ++g2)
                #pragma unroll
                for (int c = 0; c < 4; ++c)
                    ga[mt][g2][c] = 0.f;
        const char* gwp = (const char*)g_Wgh + lane * 16;
        #pragma unroll 4
        for (int ks = 0; ks < 16; ++ks) {
            uint4 A0 = *(const uint4*)(ap + ks * 2048);
            uint4 A1 = *(const uint4*)(ap + ks * 2048 + 512);
            uint4 G  = __ldg((const uint4*)(gwp + ks * 512));
            const uint32_t* ua0 = (const uint32_t*)&A0;
            const uint32_t* ua1 = (const uint32_t*)&A1;
            mma_f16(ga[0][0], ua0, G.x, G.y);
            mma_f16(ga[0][1], ua0, G.z, G.w);
            mma_f16(ga[1][0], ua1, G.x, G.y);
            mma_f16(ga[1][1], ua1, G.z, G.w);
        }
        float bg0a = bg[tig * 2],     bg0b = bg[tig * 2 + 1];
        float bg1a = bg[8 + tig * 2], bg1b = bg[9 + tig * 2];
        #pragma unroll
        for (int mt = 0; mt < 2; ++mt) {
            #pragma unroll
            for (int hf = 0; hf < 2; ++hf) {
                int row = m0 + mt * 16 + hf * 8 + gid;
                float l0a = ga[mt][0][hf * 2]     + bg0a;
                float l0b = ga[mt][0][hf * 2 + 1] + bg0b;
                float l1a = ga[mt][1][hf * 2]     + bg1a;
                float l1b = ga[mt][1][hf * 2 + 1] + bg1b;
                float mx0 = fmaxf(l0a, l0b);
                mx0 = fmaxf(mx0, __shfl_xor_sync(0xffffffffu, mx0, 1));
                mx0 = fmaxf(mx0, __shfl_xor_sync(0xffffffffu, mx0, 2));
                float e0a = __expf(l0a - mx0), e0b = __expf(l0b - mx0);
                float s0 = e0a + e0b;
                s0 += __shfl_xor_sync(0xffffffffu, s0, 1);
                s0 += __shfl_xor_sync(0xffffffffu, s0, 2);
                float inv0 = 1.f / s0;
                gs[row * 17 + tig * 2]     = e0a * inv0;
                gs[row * 17 + tig * 2 + 1] = e0b * inv0;
                float mx1 = fmaxf(l1a, l1b);
                mx1 = fmaxf(mx1, __shfl_xor_sync(0xffffffffu, mx1, 1));
                mx1 = fmaxf(mx1, __shfl_xor_sync(0xffffffffu, mx1, 2));
                float e1a = __expf(l1a - mx1), e1b = __expf(l1b - mx1);
                float s1 = e1a + e1b;
                s1 += __shfl_xor_sync(0xffffffffu, s1, 1);
                s1 += __shfl_xor_sync(0xffffffffu, s1, 2);
                float inv1 = 1.f / s1;
                gs[row * 17 + 8 + tig * 2] = e1a * inv1;
                gs[row * 17 + 9 + tig * 2] = e1b * inv1;
            }
        }
    }
    __syncthreads();
    // ======= no further barriers: pure dataflow from here on =======

    // interleaved pair mainloop: experts ea, ea+1 share A fragment loads
    auto run_pair = [&](int ea, float (&acca)[2][4][4], float (&accb)[2][4][4]) {
        const char* bpa = bbase + (size_t)ea * 65536;
        const char* bpb = bpa + 65536;
        #pragma unroll 2
        for (int ks = 0; ks < 16; ++ks) {
            uint4 A0 = *(const uint4*)(ap + ks * 2048);
            uint4 A1 = *(const uint4*)(ap + ks * 2048 + 512);
            uint4 B0 = __ldg((const uint4*)(bpa + ks * 4096));
            uint4 B1 = __ldg((const uint4*)(bpa + ks * 4096 + 512));
            uint4 C0 = __ldg((const uint4*)(bpb + ks * 4096));
            uint4 C1 = __ldg((const uint4*)(bpb + ks * 4096 + 512));
            const uint32_t* ua0 = (const uint32_t*)&A0;
            const uint32_t* ua1 = (const uint32_t*)&A1;
            mma_f16(acca[0][0], ua0, B0.x, B0.y);
            mma_f16(acca[0][1], ua0, B0.z, B0.w);
            mma_f16(acca[0][2], ua0, B1.x, B1.y);
            mma_f16(acca[0][3], ua0, B1.z, B1.w);
            mma_f16(acca[1][0], ua1, B0.x, B0.y);
            mma_f16(acca[1][1], ua1, B0.z, B0.w);
            mma_f16(acca[1][2], ua1, B1.x, B1.y);
            mma_f16(acca[1][3], ua1, B1.z, B1.w);
            mma_f16(accb[0][0], ua0, C0.x, C0.y);
            mma_f16(accb[0][1], ua0, C0.z, C0.w);
            mma_f16(accb[0][2], ua0, C1.x, C1.y);
            mma_f16(accb[0][3], ua0, C1.z, C1.w);
            mma_f16(accb[1][0], ua1, C0.x, C0.y);
            mma_f16(accb[1][1], ua1, C0.z, C0.w);
            mma_f16(accb[1][2], ua1, C1.x, C1.y);
            mma_f16(accb[1][3], ua1, C1.z, C1.w);
        }
    };

    // task-expert epilogue: bias + ReLU + gate-weighted accumulate into tw
    auto epi_task = [&](float (&acc)[2][4][4], float (&tw)[2][4][4],
                        int e, int gcol) {
        #pragma unroll
        for (int mt = 0; mt < 2; ++mt) {
            int rA = m0 + mt * 16 + gid;
            int rB = rA + 8;
            float gA = gs[rA * 17 + gcol];
            float gB = gs[rB * 17 + gcol];
            #pragma unroll
            for (int nt = 0; nt < 4; ++nt) {
                int h = hb * 32 + nt * 8 + tig * 2;
                float b0 = bs[e * H_DIM + h];
                float b1 = bs[e * H_DIM + h + 1];
                tw[mt][nt][0] += gA * fmaxf(acc[mt][nt][0] + b0, 0.f);
                tw[mt][nt][1] += gA * fmaxf(acc[mt][nt][1] + b1, 0.f);
                tw[mt][nt][2] += gB * fmaxf(acc[mt][nt][2] + b0, 0.f);
                tw[mt][nt][3] += gB * fmaxf(acc[mt][nt][3] + b1, 0.f);
            }
        }
    };

    auto writeout = [&](float (&tw)[2][4][4], int t) {
        #pragma unroll
        for (int mt = 0; mt < 2; ++mt) {
            size_t rA = (size_t)row0 + m0 + mt * 16 + gid;
            float* baseA = out + ((size_t)t * Btot + rA) * H_DIM;
            float* baseB = baseA + 8 * H_DIM;
            #pragma unroll
            for (int nt = 0; nt < 4; ++nt) {
                int h = hb * 32 + nt * 8 + tig * 2;
                *(float2*)(baseA + h) = make_float2(tw[mt][nt][0], tw[mt][nt][1]);
                *(float2*)(baseB + h) = make_float2(tw[mt][nt][2], tw[mt][nt][3]);
            }
        }
    };

    // ---- phase 1: task-0 experts 4..7, interleaved pairs, tw0 only ----
    float tw0[2][4][4];
    #pragma unroll
    for (int mt = 0; mt < 2; ++mt)
        #pragma unroll
        for (int nt = 0; nt < 4; ++nt)
            #pragma unroll
            for (int c = 0; c < 4; ++c)
                tw0[mt][nt][c] = 0.f;

    #pragma unroll 1
    for (int ea = 4; ea < 8; ea += 2) {
        float acca[2][4][4], accb[2][4][4];
        #pragma unroll
        for (int mt = 0; mt < 2; ++mt)
            #pragma unroll
            for (int nt = 0; nt < 4; ++nt)
                #pragma unroll
                for (int c = 0; c < 4; ++c) {
                    acca[mt][nt][c] = 0.f; accb[mt][nt][c] = 0.f;
                }
        run_pair(ea, acca, accb);
        epi_task(acca, tw0, ea,     ea);      // task0 gate col = e
        epi_task(accb, tw0, ea + 1, ea + 1);
    }

    // ---- phase 2: shared experts 0..3, single, tw0 + tw1 ----
    float tw1[2][4][4];
    #pragma unroll
    for (int mt = 0; mt < 2; ++mt)
        #pragma unroll
        for (int nt = 0; nt < 4; ++nt)
            #pragma unroll
            for (int c = 0; c < 4; ++c)
                tw1[mt][nt][c] = 0.f;

    #pragma unroll 1
    for (int e = 0; e < N_SHARE; ++e) {
        float acc[2][4][4];
        #pragma unroll
        for (int mt = 0; mt < 2; ++mt)
            #pragma unroll
            for (int nt = 0; nt < 4; ++nt)
                #pragma unroll
                for (int c = 0; c < 4; ++c)
                    acc[mt][nt][c] = 0.f;
        const char* bp = bbase + (size_t)e * 65536;
        #pragma unroll 4
        for (int ks = 0; ks < 16; ++ks) {
            uint4 A0 = *(const uint4*)(ap + ks * 2048);
            uint4 A1 = *(const uint4*)(ap + ks * 2048 + 512);
            uint4 B0 = __ldg((const uint4*)(bp + ks * 4096));
            uint4 B1 = __ldg((const uint4*)(bp + ks * 4096 + 512));
            const uint32_t* ua0 = (const uint32_t*)&A0;
            const uint32_t* ua1 = (const uint32_t*)&A1;
            mma_f16(acc[0][0], ua0, B0.x, B0.y);
            mma_f16(acc[0][1], ua0, B0.z, B0.w);
            mma_f16(acc[0][2], ua0, B1.x, B1.y);
            mma_f16(acc[0][3], ua0, B1.z, B1.w);
            mma_f16(acc[1][0], ua1, B0.x, B0.y);
            mma_f16(acc[1][1], ua1, B0.z, B0.w);
            mma_f16(acc[1][2], ua1, B1.x, B1.y);
            mma_f16(acc[1][3], ua1, B1.z, B1.w);
        }
        #pragma unroll
        for (int mt = 0; mt < 2; ++mt) {
            int rA = m0 + mt * 16 + gid;
            int rB = rA + 8;
            float gA0 = gs[rA * 17 + e],     gB0 = gs[rB * 17 + e];
            float gA1 = gs[rA * 17 + 8 + e], gB1 = gs[rB * 17 + 8 + e];
            #pragma unroll
            for (int nt = 0; nt < 4; ++nt) {
                int h = hb * 32 + nt * 8 + tig * 2;
                float b0 = bs[e * H_DIM + h];
                float b1 = bs[e * H_DIM + h + 1];
                float v0 = fmaxf(acc[mt][nt][0] + b0, 0.f);
                float v1 = fmaxf(acc[mt][nt][1] + b1, 0.f);
                float v2 = fmaxf(acc[mt][nt][2] + b0, 0.f);
                float v3 = fmaxf(acc[mt][nt][3] + b1, 0.f);
                tw0[mt][nt][0] += gA0 * v0;  tw0[mt][nt][1] += gA0 * v1;
                tw0[mt][nt][2] += gB0 * v2;  tw0[mt][nt][3] += gB0 * v3;
                tw1[mt][nt][0] += gA1 * v0;  tw1[mt][nt][1] += gA1 * v1;
                tw1[mt][nt][2] += gB1 * v2;  tw1[mt][nt][3] += gB1 * v3;
            }
        }
    }

    // task 0 complete -> write it out, freeing tw0
    writeout(tw0, 0);

    // ---- phase 3: task-1 experts 8..11, interleaved pairs, tw1 only ----
    #pragma unroll 1
    for (int ea = 8; ea < 12; ea += 2) {
        float acca[2][4][4], accb[2][4][4];
        #pragma unroll
        for (int mt = 0; mt < 2; ++mt)
            #pragma unroll
            for (int nt = 0; nt < 4; ++nt)
                #pragma unroll
                for (int c = 0; c < 4; ++c) {
                    acca[mt][nt][c] = 0.f; accb[mt][nt][c] = 0.f;
                }
        run_pair(ea, acca, accb);
        epi_task(acca, tw1, ea,     ea + 4);  // task1 gate col = e + 4
        epi_task(accb, tw1, ea + 1, ea + 5);
    }

    writeout(tw1, 1);
}

extern "C" void kernel_launch(void* const* d_in, const int* in_sizes, int n_in,
                              void* d_out, int out_size) {
    const float* x   = (const float*)d_in[0];
    const float* Wsh = (const float*)d_in[1];
    const float* bsh = (const float*)d_in[2];
    const float* Wtk = (const float*)d_in[3];
    const float* btk = (const float*)d_in[4];
    const float* Wg  = (const float*)d_in[5];
    const float* bg  = (const float*)d_in[6];
    float* out = (float*)d_out;

    int Btot = in_sizes[0] / D_IN;                // 32768
    int nslots = N_EXPERTS * 4096 + 512;          // 49664
    dmoe_wprep<<<(nslots + 255) / 256, 256>>>(Wsh, Wtk, Wg);

    cudaFuncSetAttribute(dmoe_fused_kernel,
                         cudaFuncAttributeMaxDynamicSharedMemorySize, SMEM_BYTES);
    dmoe_fused_kernel<<<Btot / M_TILE, THREADS, SMEM_BYTES>>>(
        x, bsh, btk, bg, out, Btot);
}